// round 6
// baseline (speedup 1.0000x reference)
#include <cuda_runtime.h>
#include <cstdint>

#define BATCH 128
#define T1    196
#define T2    392
#define ENC   1024
#define DEC   512
#define VV    98
#define MM    294

// GEMM tiles
#define BM 128
#define BN 128
#define BK 32                  // K floats per slab (128 B rows)
#define NSLAB (ENC / BK)       // 32
#define NSTAGE 3
#define A_STAGE (BM * 128)     // 16 KB
#define B_STAGE (BN * 128)     // 16 KB
#define SMEM_DYN (NSTAGE * (A_STAGE + B_STAGE))   // 96 KB

#define N_TILES  ((BATCH * VV / BM) * (DEC / BN))  // 392
#define FILLC    56                                 // fill CTAs (tail wave)

__device__ int g_vis[BATCH * VV];
__device__ unsigned char g_msk[BATCH * T2];  // 1 = masked

// ---------------------------------------------------------------------------
__device__ __forceinline__ uint32_t smem_u32(const void* p) {
    uint32_t a;
    asm("{ .reg .u64 t; cvta.to.shared.u64 t, %1; cvt.u32.u64 %0, t; }"
        : "=r"(a) : "l"(p));
    return a;
}
__device__ __forceinline__ void cp16(uint32_t dst, const void* src) {
    asm volatile("cp.async.cg.shared.global [%0], [%1], 16;"
                 :: "r"(dst), "l"(src));
}
#define CP_COMMIT() asm volatile("cp.async.commit_group;" ::: "memory")
#define CP_WAIT(n)  asm volatile("cp.async.wait_group %0;" :: "n"(n) : "memory")

__device__ __forceinline__ void ldsm4(uint32_t* r, uint32_t addr) {
    asm volatile("ldmatrix.sync.aligned.m8n8.x4.shared.b16 {%0,%1,%2,%3}, [%4];"
                 : "=r"(r[0]), "=r"(r[1]), "=r"(r[2]), "=r"(r[3]) : "r"(addr));
}
__device__ __forceinline__ void mma_tf32(float* c, const uint32_t* a,
                                         uint32_t b0, uint32_t b1) {
    asm volatile(
        "mma.sync.aligned.m16n8k8.row.col.f32.tf32.tf32.f32 "
        "{%0,%1,%2,%3}, {%4,%5,%6,%7}, {%8,%9}, {%0,%1,%2,%3};"
        : "+f"(c[0]), "+f"(c[1]), "+f"(c[2]), "+f"(c[3])
        : "r"(a[0]), "r"(a[1]), "r"(a[2]), "r"(a[3]), "r"(b0), "r"(b1));
}

// ---------------------------------------------------------------------------
// K1: per-batch visibility map + masked flags (+ dtype detect per block)
// ---------------------------------------------------------------------------
__global__ void build_map_kernel(const void* __restrict__ masked_ids) {
    __shared__ int flag[T2];
    __shared__ int s[512];
    __shared__ int s_any;
    const int b = blockIdx.x;
    const int tid = threadIdx.x;

    if (tid == 0) s_any = 0;
    if (tid < T2) flag[tid] = 1;
    __syncthreads();

    // dtype detect: int64 ids < 392 => all odd 32-bit words zero
    {
        const int* w = (const int*)masked_ids;
        int acc = 0;
        for (int i = 1 + 2 * tid; i < 1000; i += 2 * 512) acc |= w[i];
        if (acc) atomicOr(&s_any, 1);
    }
    __syncthreads();
    const int is64 = (s_any == 0);

    for (int i = tid; i < MM; i += 512) {
        int id;
        if (is64) id = (int)((const long long*)masked_ids)[(size_t)b * MM + i];
        else      id = ((const int*)masked_ids)[(size_t)b * MM + i];
        flag[id] = 0;
    }
    __syncthreads();

    const int f = (tid < T2) ? flag[tid] : 0;
    if (tid < T2) g_msk[b * T2 + tid] = (unsigned char)(1 - f);
    s[tid] = f;
    __syncthreads();
    #pragma unroll
    for (int off = 1; off < 512; off <<= 1) {
        int v = (tid >= off) ? s[tid - off] : 0;
        __syncthreads();
        s[tid] += v;
        __syncthreads();
    }
    if (f) g_vis[b * VV + (s[tid] - f)] = tid;
}

// ---------------------------------------------------------------------------
// Fill role: grid-strided over masked rows; writes mask_token+pos+view.
// ---------------------------------------------------------------------------
__device__ void fill_role(int fidx, const float* __restrict__ mask_token,
                          const float* __restrict__ pos_embed,
                          const float* __restrict__ view_embed,
                          float4* __restrict__ out) {
    const int D4 = DEC / 4;  // 128
    const float4* mt4  = (const float4*)mask_token;
    const float4* pos4 = (const float4*)pos_embed;
    const float4* ve4  = (const float4*)view_embed;

    const int total = BATCH * T2;  // rows
    // each step handles one (b,t) row chunk of 128 float4 split over... simpler:
    // iterate rows; each row = 128 float4 written by 256 threads in 2 passes? 
    // Use: row per (fidx, iter), 256 threads cover 128 float4 with stride 2? 
    // Cleaner: flat index over total*D4 with grid stride.
    const long long N = (long long)total * D4;
    for (long long i = (long long)fidx * 256 + threadIdx.x; i < N;
         i += (long long)FILLC * 256) {
        const int row = (int)(i >> 7);          // b*T2 + t
        if (!g_msk[row]) continue;
        const int d4 = (int)(i & 127);
        const int t = row % T2;
        float4 m = mt4[d4];
        float4 p = pos4[t * D4 + d4];
        float4 v = ve4[(t >= T1 ? D4 : 0) + d4];
        out[i] = make_float4(m.x + p.x + v.x, m.y + p.y + v.y,
                             m.z + p.z + v.z, m.w + p.w + v.w);
    }
}

// ---------------------------------------------------------------------------
// Gemm role: one 128x128 tile, tf32 mma.sync, 3-stage pipeline, 1 sync/slab,
// fused scatter epilogue.
// ---------------------------------------------------------------------------
__device__ void gemm_role(int tile, uint32_t A0, uint32_t B0,
                          const float* __restrict__ x,
                          const float* __restrict__ W,
                          const float* __restrict__ bias,
                          const float* __restrict__ pos_embed,
                          const float* __restrict__ view_embed,
                          float* __restrict__ out) {
    const int tid = threadIdx.x;
    const int wid = tid >> 5, lid = tid & 31;
    const int wm = wid >> 1, wn = wid & 1;
    const int m0 = (tile >> 2) * BM;
    const int n0 = (tile & 3) * BN;

    // loader mapping: thread -> row, 4 x 16B chunks
    const int rA = tid >> 1;
    const int q0 = (tid & 1) * 4;
    const uint32_t rsw = (rA & 7) << 4;
    const float* xsrc = x + (size_t)(m0 + rA) * ENC + q0 * 4;
    const float* wsrc = W + (size_t)(n0 + rA) * ENC + q0 * 4;
    const uint32_t adst = rA * 128 + ((q0 * 16) ^ rsw);

    // fragment addresses
    const int a_row0 = wm * 32 + ((lid >> 3 & 1) << 3) + (lid & 7);
    const uint32_t a_kb = ((lid >> 4) & 1) * 16;
    const uint32_t a_swz0 = (a_row0 & 7) << 4;
    const uint32_t a_base0 = a_row0 * 128;
    const int b_row0 = wn * 64 + (((lid >> 4) & 1) << 3) + (lid & 7);
    const uint32_t b_kb = ((lid >> 3) & 1) * 16;
    const uint32_t b_swz0 = (b_row0 & 7) << 4;
    const uint32_t b_base0 = b_row0 * 128;

    float acc[2][8][4];
    #pragma unroll
    for (int f = 0; f < 2; f++)
        #pragma unroll
        for (int nf = 0; nf < 8; nf++)
            #pragma unroll
            for (int i = 0; i < 4; i++) acc[f][nf][i] = 0.f;

    // prologue: slabs 0,1 -> buffers 0,1
    #pragma unroll
    for (int st = 0; st < NSTAGE - 1; st++) {
        #pragma unroll
        for (int i = 0; i < 4; i++) {
            cp16(A0 + st * A_STAGE + (adst ^ (i * 16)), xsrc + st * BK + i * 4);
            cp16(B0 + st * B_STAGE + (adst ^ (i * 16)), wsrc + st * BK + i * 4);
        }
        CP_COMMIT();
    }

    int buf = 0;
    for (int k = 0; k < NSLAB; k++) {
        CP_WAIT(NSTAGE - 2);       // slab k landed (this thread's part)
        __syncthreads();           // all parts visible; buf (k+2)%3 reusable

        if (k + 2 < NSLAB) {       // load slab k+2 into buffer (k+2)%3
            const int nb = (buf + 2 >= NSTAGE) ? buf + 2 - NSTAGE : buf + 2;
            #pragma unroll
            for (int i = 0; i < 4; i++) {
                cp16(A0 + nb * A_STAGE + (adst ^ (i * 16)),
                     xsrc + (k + 2) * BK + i * 4);
                cp16(B0 + nb * B_STAGE + (adst ^ (i * 16)),
                     wsrc + (k + 2) * BK + i * 4);
            }
        }
        CP_COMMIT();               // empty commits keep group accounting

        const uint32_t As = A0 + buf * A_STAGE;
        const uint32_t Bs = B0 + buf * B_STAGE;
        #pragma unroll
        for (int ks = 0; ks < 4; ks++) {
            const uint32_t k0b = ks * 32;
            uint32_t a[2][4], bb[4][4];
            #pragma unroll
            for (int f = 0; f < 2; f++)
                ldsm4(a[f], As + a_base0 + f * (16 * 128) +
                             ((a_kb + k0b) ^ a_swz0));
            #pragma unroll
            for (int p = 0; p < 4; p++)
                ldsm4(bb[p], Bs + b_base0 + p * (16 * 128) +
                             ((b_kb + k0b) ^ b_swz0));
            #pragma unroll
            for (int f = 0; f < 2; f++)
                #pragma unroll
                for (int p = 0; p < 4; p++) {
                    mma_tf32(acc[f][2 * p],     a[f], bb[p][0], bb[p][1]);
                    mma_tf32(acc[f][2 * p + 1], a[f], bb[p][2], bb[p][3]);
                }
        }
        buf = (buf + 1 == NSTAGE) ? 0 : buf + 1;
    }

    // fused scatter epilogue
    const int g  = lid >> 2;
    const int nc = 2 * (lid & 3);
    const int nbase = n0 + wn * 64;
    #pragma unroll
    for (int f = 0; f < 2; f++) {
        #pragma unroll
        for (int h = 0; h < 2; h++) {
            const int m = m0 + wm * 32 + f * 16 + h * 8 + g;
            const int b = m / VV;
            const int t = g_vis[m];
            const float* ve   = view_embed + (t >= T1 ? DEC : 0) + nbase;
            const float* bi   = bias + nbase;
            const float* prow = pos_embed + (size_t)t * DEC + nbase;
            float* orow = out + ((size_t)b * T2 + t) * DEC + nbase;
            #pragma unroll
            for (int nf = 0; nf < 8; nf++) {
                const int n = nf * 8 + nc;
                float2 biv = *(const float2*)(bi + n);
                float2 pov = *(const float2*)(prow + n);
                float2 vev = *(const float2*)(ve + n);
                float2 r;
                r.x = acc[f][nf][2 * h + 0] + biv.x + pov.x + vev.x;
                r.y = acc[f][nf][2 * h + 1] + biv.y + pov.y + vev.y;
                *(float2*)(orow + n) = r;
            }
        }
    }
}

// ---------------------------------------------------------------------------
// Combined kernel: first N_TILES CTAs do gemm; the rest do the masked fill
// (they land in the second wave, overlapping the gemm tail).
// ---------------------------------------------------------------------------
__global__ __launch_bounds__(256, 2)
void worker_kernel(const float* __restrict__ x,
                   const float* __restrict__ W,
                   const float* __restrict__ bias,
                   const float* __restrict__ mask_token,
                   const float* __restrict__ pos_embed,
                   const float* __restrict__ view_embed,
                   float* __restrict__ out) {
    extern __shared__ char smem_raw[];
    const uint32_t A0 = smem_u32(smem_raw);
    const uint32_t B0 = A0 + NSTAGE * A_STAGE;

    if (blockIdx.x < N_TILES)
        gemm_role(blockIdx.x, A0, B0, x, W, bias, pos_embed, view_embed, out);
    else
        fill_role(blockIdx.x - N_TILES, mask_token, pos_embed, view_embed,
                  (float4*)out);
}

// ---------------------------------------------------------------------------
extern "C" void kernel_launch(void* const* d_in, const int* in_sizes, int n_in,
                              void* d_out, int out_size) {
    const float* x          = (const float*)d_in[0];
    const void*  masked_ids = d_in[1];
    const float* W          = (const float*)d_in[2];
    const float* bias       = (const float*)d_in[3];
    const float* mask_token = (const float*)d_in[4];
    const float* pos_embed  = (const float*)d_in[5];
    const float* view_embed = (const float*)d_in[6];
    float* out = (float*)d_out;

    build_map_kernel<<<BATCH, 512>>>(masked_ids);

    static int smem_set = 0;
    if (!smem_set) {
        cudaFuncSetAttribute(worker_kernel,
                             cudaFuncAttributeMaxDynamicSharedMemorySize, SMEM_DYN);
        smem_set = 1;
    }
    worker_kernel<<<N_TILES + FILLC, 256, SMEM_DYN>>>(
        x, W, bias, mask_token, pos_embed, view_embed, out);
}

// round 7
// speedup vs baseline: 2.0215x; 2.0215x over previous
#include <cuda_runtime.h>
#include <cuda_fp16.h>
#include <cstdint>

#define BATCH 128
#define T1    196
#define T2    392
#define ENC   1024
#define DEC   512
#define VV    98
#define MM    294

// fp16 GEMM tiles
#define BM 128
#define BN 128
#define BKH 64                 // K halves per slab (128 B rows)
#define NSLAB (ENC / BKH)      // 16
#define A_STAGE (BM * 128)     // 16 KB
#define B_STAGE (BN * 128)     // 16 KB
#define SMEM_DYN (2 * (A_STAGE + B_STAGE))  // 64 KB

#define N_TILES ((BATCH * VV / BM) * (DEC / BN))  // 392

// prep-kernel roles
#define MAPB   BATCH           // 128 map+fill blocks
#define CVXB   256             // x-convert blocks
#define CVWB   8               // W-convert blocks
#define PREPB  (MAPB + CVXB + CVWB)

__device__ int g_vis[BATCH * VV];
__device__ __align__(16) __half g_xh[(size_t)BATCH * VV * ENC];  // 25.7 MB
__device__ __align__(16) __half g_wh[DEC * ENC];                 // 1 MB

// ---------------------------------------------------------------------------
__device__ __forceinline__ uint32_t smem_u32(const void* p) {
    uint32_t a;
    asm("{ .reg .u64 t; cvta.to.shared.u64 t, %1; cvt.u32.u64 %0, t; }"
        : "=r"(a) : "l"(p));
    return a;
}
__device__ __forceinline__ void cp16(uint32_t dst, const void* src) {
    asm volatile("cp.async.cg.shared.global [%0], [%1], 16;"
                 :: "r"(dst), "l"(src));
}
#define CP_COMMIT() asm volatile("cp.async.commit_group;" ::: "memory")
#define CP_WAIT(n)  asm volatile("cp.async.wait_group %0;" :: "n"(n) : "memory")

__device__ __forceinline__ void ldsm4(uint32_t* r, uint32_t addr) {
    asm volatile("ldmatrix.sync.aligned.m8n8.x4.shared.b16 {%0,%1,%2,%3}, [%4];"
                 : "=r"(r[0]), "=r"(r[1]), "=r"(r[2]), "=r"(r[3]) : "r"(addr));
}
__device__ __forceinline__ void mma_f16(float* c, const uint32_t* a,
                                        uint32_t b0, uint32_t b1) {
    asm volatile(
        "mma.sync.aligned.m16n8k16.row.col.f32.f16.f16.f32 "
        "{%0,%1,%2,%3}, {%4,%5,%6,%7}, {%8,%9}, {%0,%1,%2,%3};"
        : "+f"(c[0]), "+f"(c[1]), "+f"(c[2]), "+f"(c[3])
        : "r"(a[0]), "r"(a[1]), "r"(a[2]), "r"(a[3]), "r"(b0), "r"(b1));
}

// ---------------------------------------------------------------------------
// Prep kernel, 512 threads/block:
//  blocks [0,128):   per-batch map (g_vis) + masked-row fill of out
//  blocks [128,384): convert x  fp32 -> fp16 (g_xh)
//  blocks [384,392): convert W  fp32 -> fp16 (g_wh)
// ---------------------------------------------------------------------------
__global__ __launch_bounds__(512)
void prep_kernel(const float* __restrict__ x,
                 const void* __restrict__ masked_ids,
                 const float* __restrict__ W,
                 const float* __restrict__ mask_token,
                 const float* __restrict__ pos_embed,
                 const float* __restrict__ view_embed,
                 float4* __restrict__ out) {
    const int bid = blockIdx.x;
    const int tid = threadIdx.x;

    if (bid < MAPB) {
        // ---- map + masked fill for batch b
        __shared__ int flag[T2];
        __shared__ int s[512];
        __shared__ int s_any;
        const int b = bid;

        if (tid == 0) s_any = 0;
        if (tid < T2) flag[tid] = 1;
        __syncthreads();

        // dtype detect: int64 ids < 392 => all odd 32-bit words zero
        {
            const int* w = (const int*)masked_ids;
            int acc = 0;
            for (int i = 1 + 2 * tid; i < 1000; i += 2 * 512) acc |= w[i];
            if (acc) atomicOr(&s_any, 1);
        }
        __syncthreads();
        const int is64 = (s_any == 0);

        for (int i = tid; i < MM; i += 512) {
            int id;
            if (is64) id = (int)((const long long*)masked_ids)[(size_t)b * MM + i];
            else      id = ((const int*)masked_ids)[(size_t)b * MM + i];
            flag[id] = 0;
        }
        __syncthreads();

        const int f = (tid < T2) ? flag[tid] : 0;
        s[tid] = f;
        __syncthreads();
        #pragma unroll
        for (int off = 1; off < 512; off <<= 1) {
            int v = (tid >= off) ? s[tid - off] : 0;
            __syncthreads();
            s[tid] += v;
            __syncthreads();
        }
        if (f) g_vis[b * VV + (s[tid] - f)] = tid;
        __syncthreads();

        // masked-row fill: out[b][t][:] = mask_token + pos + ve for flag[t]==0
        const int D4 = DEC / 4;  // 128
        const float4* mt4  = (const float4*)mask_token;
        const float4* pos4 = (const float4*)pos_embed;
        const float4* ve4  = (const float4*)view_embed;
        float4* obase = out + (size_t)b * T2 * D4;
        for (int idx = tid; idx < T2 * D4; idx += 512) {
            const int t = idx >> 7;
            if (flag[t]) continue;
            const int d4 = idx & 127;
            float4 m = mt4[d4];
            float4 p = pos4[idx];
            float4 v = ve4[(t >= T1 ? D4 : 0) + d4];
            obase[idx] = make_float4(m.x + p.x + v.x, m.y + p.y + v.y,
                                     m.z + p.z + v.z, m.w + p.w + v.w);
        }
    } else if (bid < MAPB + CVXB) {
        // ---- convert x -> g_xh (half2 pairs)
        const long long N2 = (long long)BATCH * VV * ENC / 2;  // 6.42M
        const float2* src = (const float2*)x;
        half2* dst = (half2*)g_xh;
        for (long long i = (long long)(bid - MAPB) * 512 + tid; i < N2;
             i += (long long)CVXB * 512) {
            float2 v = src[i];
            dst[i] = __floats2half2_rn(v.x, v.y);
        }
    } else {
        // ---- convert W -> g_wh
        const int N2 = DEC * ENC / 2;  // 262144
        const float2* src = (const float2*)W;
        half2* dst = (half2*)g_wh;
        for (int i = (bid - MAPB - CVXB) * 512 + tid; i < N2;
             i += CVWB * 512) {
            float2 v = src[i];
            dst[i] = __floats2half2_rn(v.x, v.y);
        }
    }
}

// ---------------------------------------------------------------------------
// fp16 mma.sync GEMM (M=12544, N=512, K=1024) + fused scatter epilogue.
// K-major fp16 smem tiles (128 B rows, SW128). 8 warps: 4m x 2n, warp tile
// 32x64. 2-stage cp.async pipeline (R3 structure).
// ---------------------------------------------------------------------------
__global__ __launch_bounds__(256, 2)
void gemm_tc_kernel(const float* __restrict__ bias,
                    const float* __restrict__ pos_embed,
                    const float* __restrict__ view_embed,
                    float* __restrict__ out) {
    extern __shared__ char smem_raw[];
    const uint32_t A0 = smem_u32(smem_raw);
    const uint32_t B0 = A0 + 2 * A_STAGE;

    const int tid = threadIdx.x;
    const int wid = tid >> 5, lid = tid & 31;
    const int wm = wid >> 1, wn = wid & 1;
    const int m0 = blockIdx.y * BM;
    const int n0 = blockIdx.x * BN;

    // loader mapping: 2 threads/row, 4 x 16B chunks each (128 B/row)
    const int rA = tid >> 1;
    const int q0 = (tid & 1) * 4;
    const uint32_t rsw = (rA & 7) << 4;
    const __half* xsrc = g_xh + (size_t)(m0 + rA) * ENC + q0 * 8;
    const __half* wsrc = g_wh + (size_t)(n0 + rA) * ENC + q0 * 8;
    const uint32_t adst = rA * 128 + ((q0 * 16) ^ rsw);

    // fragment addresses (identical mapping to tf32 version; units = bytes)
    const int a_row0 = wm * 32 + ((lid >> 3 & 1) << 3) + (lid & 7);
    const uint32_t a_kb = ((lid >> 4) & 1) * 16;
    const uint32_t a_swz0 = (a_row0 & 7) << 4;
    const uint32_t a_base0 = a_row0 * 128;
    const int b_row0 = wn * 64 + (((lid >> 4) & 1) << 3) + (lid & 7);
    const uint32_t b_kb = ((lid >> 3) & 1) * 16;
    const uint32_t b_swz0 = (b_row0 & 7) << 4;
    const uint32_t b_base0 = b_row0 * 128;

    float acc[2][8][4];
    #pragma unroll
    for (int f = 0; f < 2; f++)
        #pragma unroll
        for (int nf = 0; nf < 8; nf++)
            #pragma unroll
            for (int i = 0; i < 4; i++) acc[f][nf][i] = 0.f;

    // prologue: slabs 0,1
    #pragma unroll
    for (int st = 0; st < 2; st++) {
        #pragma unroll
        for (int i = 0; i < 4; i++) {
            cp16(A0 + st * A_STAGE + (adst ^ (i * 16)), xsrc + st * BKH + i * 8);
            cp16(B0 + st * B_STAGE + (adst ^ (i * 16)), wsrc + st * BKH + i * 8);
        }
        CP_COMMIT();
    }

    for (int k = 0; k < NSLAB; k++) {
        const int s = k & 1;
        CP_WAIT(1);
        __syncthreads();

        const uint32_t As = A0 + s * A_STAGE;
        const uint32_t Bs = B0 + s * B_STAGE;
        #pragma unroll
        for (int ks = 0; ks < 4; ks++) {       // 4 x k16 per 64-half slab
            const uint32_t k0b = ks * 32;      // 16 halves = 32 B
            uint32_t a[2][4], bb[4][4];
            #pragma unroll
            for (int f = 0; f < 2; f++)
                ldsm4(a[f], As + a_base0 + f * (16 * 128) +
                             ((a_kb + k0b) ^ a_swz0));
            #pragma unroll
            for (int p = 0; p < 4; p++)
                ldsm4(bb[p], Bs + b_base0 + p * (16 * 128) +
                             ((b_kb + k0b) ^ b_swz0));
            #pragma unroll
            for (int f = 0; f < 2; f++)
                #pragma unroll
                for (int p = 0; p < 4; p++) {
                    mma_f16(acc[f][2 * p],     a[f], bb[p][0], bb[p][1]);
                    mma_f16(acc[f][2 * p + 1], a[f], bb[p][2], bb[p][3]);
                }
        }
        __syncthreads();

        if (k + 2 < NSLAB) {
            #pragma unroll
            for (int i = 0; i < 4; i++) {
                cp16(A0 + s * A_STAGE + (adst ^ (i * 16)),
                     xsrc + (k + 2) * BKH + i * 8);
                cp16(B0 + s * B_STAGE + (adst ^ (i * 16)),
                     wsrc + (k + 2) * BKH + i * 8);
            }
        }
        CP_COMMIT();
    }

    // fused scatter epilogue
    const int g  = lid >> 2;
    const int nc = 2 * (lid & 3);
    const int nbase = n0 + wn * 64;
    #pragma unroll
    for (int f = 0; f < 2; f++) {
        #pragma unroll
        for (int h = 0; h < 2; h++) {
            const int m = m0 + wm * 32 + f * 16 + h * 8 + g;
            const int b = m / VV;
            const int t = g_vis[m];
            const float* ve   = view_embed + (t >= T1 ? DEC : 0) + nbase;
            const float* bi   = bias + nbase;
            const float* prow = pos_embed + (size_t)t * DEC + nbase;
            float* orow = out + ((size_t)b * T2 + t) * DEC + nbase;
            #pragma unroll
            for (int nf = 0; nf < 8; nf++) {
                const int n = nf * 8 + nc;
                float2 biv = *(const float2*)(bi + n);
                float2 pov = *(const float2*)(prow + n);
                float2 vev = *(const float2*)(ve + n);
                float2 r;
                r.x = acc[f][nf][2 * h + 0] + biv.x + pov.x + vev.x;
                r.y = acc[f][nf][2 * h + 1] + biv.y + pov.y + vev.y;
                *(float2*)(orow + n) = r;
            }
        }
    }
}

// ---------------------------------------------------------------------------
extern "C" void kernel_launch(void* const* d_in, const int* in_sizes, int n_in,
                              void* d_out, int out_size) {
    const float* x          = (const float*)d_in[0];
    const void*  masked_ids = d_in[1];
    const float* W          = (const float*)d_in[2];
    const float* bias       = (const float*)d_in[3];
    const float* mask_token = (const float*)d_in[4];
    const float* pos_embed  = (const float*)d_in[5];
    const float* view_embed = (const float*)d_in[6];
    float* out = (float*)d_out;

    prep_kernel<<<PREPB, 512>>>(x, masked_ids, W, mask_token, pos_embed,
                                view_embed, (float4*)out);

    static int smem_set = 0;
    if (!smem_set) {
        cudaFuncSetAttribute(gemm_tc_kernel,
                             cudaFuncAttributeMaxDynamicSharedMemorySize, SMEM_DYN);
        smem_set = 1;
    }
    dim3 grid(DEC / BN, (BATCH * VV) / BM);  // (4, 98)
    gemm_tc_kernel<<<grid, 256, SMEM_DYN>>>(bias, pos_embed, view_embed, out);
}